// round 2
// baseline (speedup 1.0000x reference)
#include <cuda_runtime.h>

#define ULL unsigned long long

// ---------- packed f32x2 helpers (sm_100+ PTX) ----------
__device__ __forceinline__ void fma2(ULL &acc, ULL a, ULL b) {
    asm("fma.rn.f32x2 %0, %1, %2, %0;" : "+l"(acc) : "l"(a), "l"(b));
}
__device__ __forceinline__ ULL add2(ULL a, ULL b) {
    ULL r; asm("add.rn.f32x2 %0, %1, %2;" : "=l"(r) : "l"(a), "l"(b)); return r;
}
__device__ __forceinline__ float2 unpack2(ULL v) {
    float2 r; asm("mov.b64 {%0, %1}, %2;" : "=f"(r.x), "=f"(r.y) : "l"(v)); return r;
}
__device__ __forceinline__ ULL pack2(float x, float y) {
    ULL r; asm("mov.b64 %0, {%1, %2};" : "=l"(r) : "f"(x), "f"(y)); return r;
}

// ---------- problem dims ----------
#define MM 16
#define NN 4096
#define HH 32
#define DD 128
#define PP 8192
#define PTOT (PP + MM)        // 8208
#define NCHUNK 17             // 16 chunks of 512 cache + 1 chunk of new tokens

// ---------- device scratch (allocation-free rule: __device__ globals) ----------
__device__ float g_invr[MM];
__device__ float g_q[MM * NN];
__device__ float g_k[MM * NN];
__device__ float g_v[MM * NN];
__device__ float g_nump[NCHUNK * HH * MM * DD];   // per-chunk O partials
__device__ float g_denp[NCHUNK * HH * MM];        // per-chunk softmax denominators

// ============================================================
// K1: per-row inverse RMS
// ============================================================
__global__ __launch_bounds__(256) void rms_kernel(const float* __restrict__ X) {
    int m = blockIdx.x;
    int t = threadIdx.x;
    float s = 0.f;
    const float4* Xr = (const float4*)(X + m * NN);
    for (int i = t; i < NN / 4; i += 256) {
        float4 v = Xr[i];
        s += v.x * v.x + v.y * v.y + v.z * v.z + v.w * v.w;
    }
    __shared__ float red[8];
    for (int o = 16; o; o >>= 1) s += __shfl_xor_sync(0xffffffffu, s, o);
    if ((t & 31) == 0) red[t >> 5] = s;
    __syncthreads();
    if (t == 0) {
        float tot = 0.f;
        #pragma unroll
        for (int i = 0; i < 8; i++) tot += red[i];
        g_invr[m] = rsqrtf(tot * (1.0f / (float)NN));
    }
}

// ============================================================
// K2: fused QKV projection.  out[m][j] = sum_k xnorm[m][k] * W[j][k]
// 768 blocks: 256 per weight, each covers 16 j columns (2 per warp).
// k-pair-packed f32x2 accumulation; lo+hi folded after lane reduction.
// ============================================================
__global__ __launch_bounds__(256) void qkv_kernel(
    const float* __restrict__ X,
    const float* __restrict__ Wq,
    const float* __restrict__ Wk,
    const float* __restrict__ Wv)
{
    __shared__ float xs[MM][128];   // rows 512B: lanes cover full row -> conflict-free

    int b = blockIdx.x;
    int wsel  = b >> 8;            // 0=q, 1=k, 2=v
    int jbase = (b & 255) << 4;    // 16 columns per block
    const float* W   = (wsel == 0) ? Wq : (wsel == 1) ? Wk : Wv;
    float*       Out = (wsel == 0) ? g_q : (wsel == 1) ? g_k : g_v;

    int t = threadIdx.x, warp = t >> 5, lane = t & 31;
    int j0 = jbase + warp * 2;
    const float* Wp0 = W + (size_t)j0 * NN;
    const float* Wp1 = Wp0 + NN;

    ULL acc0[MM], acc1[MM];
    #pragma unroll
    for (int m = 0; m < MM; m++) { acc0[m] = 0ull; acc1[m] = 0ull; }

    for (int kc = 0; kc < NN / 128; kc++) {
        int base = kc * 128;
        // cooperative load + rms-scale of X chunk
        #pragma unroll
        for (int r = 0; r < 2; r++) {
            int idx = t + r * 256;          // 0..511
            int m = idx >> 5, kq = idx & 31;
            float4 v = *(const float4*)(X + m * NN + base + kq * 4);
            float sc = g_invr[m];
            v.x *= sc; v.y *= sc; v.z *= sc; v.w *= sc;
            *(float4*)&xs[m][kq * 4] = v;
        }
        __syncthreads();

        ulonglong2 w0 = *(const ulonglong2*)(Wp0 + base + lane * 4);
        ulonglong2 w1 = *(const ulonglong2*)(Wp1 + base + lane * 4);
        #pragma unroll
        for (int m = 0; m < MM; m++) {
            const ULL* xp = (const ULL*)&xs[m][lane * 4];
            ULL xa = xp[0], xb = xp[1];
            fma2(acc0[m], xa, w0.x); fma2(acc0[m], xb, w0.y);
            fma2(acc1[m], xa, w1.x); fma2(acc1[m], xb, w1.y);
        }
        __syncthreads();
    }

    // lane reduction (packed), then fold k-pair
    #pragma unroll
    for (int m = 0; m < MM; m++) {
        ULL a = acc0[m], c = acc1[m];
        #pragma unroll
        for (int o = 16; o; o >>= 1) {
            a = add2(a, __shfl_xor_sync(0xffffffffu, a, o));
            c = add2(c, __shfl_xor_sync(0xffffffffu, c, o));
        }
        if (lane == 0) {
            float2 fa = unpack2(a), fc = unpack2(c);
            Out[m * NN + j0]     = fa.x + fa.y;
            Out[m * NN + j0 + 1] = fc.x + fc.y;
        }
    }
}

// ============================================================
// K3: attention partials over a P-chunk (flash-style, no atomics)
// grid (17 chunks, 32 heads), 128 threads.
// K/V smem tiles use XOR-(p>>2) swizzle on 16B chunks (row stride 512B
// would alias banks for the strided score access p in {j, j+4, ...}).
// ============================================================
#define TPp 32
__device__ __forceinline__ int SWZ(int r, int c) { return c ^ ((r >> 2) & 7); }

__global__ __launch_bounds__(128) void attn_kernel(
    const float* __restrict__ cacheK,
    const float* __restrict__ cacheV)
{
    __shared__ float qs[MM][132];          // padded: 4 distinct m rows per warp, conflict-free
    __shared__ float Ks[TPp * 128];        // swizzled
    __shared__ float Vs[TPp * 128];        // swizzled
    __shared__ float st[TPp][20];          // exp-scores, padded rows (80B, 16B aligned)

    int chunk = blockIdx.x;                // 0..16
    int h     = blockIdx.y;
    int t = threadIdx.x, warp = t >> 5, lane = t & 31;
    int sm = t >> 3;                       // m for score phase (0..15)
    int pq = t & 7;                        // p-quad for score phase

    // load q tile for this head
    #pragma unroll
    for (int i = 0; i < 4; i++) {
        int idx = t + i * 128;
        int m = idx >> 5, c = idx & 31;
        *(float4*)&qs[m][c * 4] =
            *(const float4*)(g_q + m * NN + h * DD + c * 4);
    }

    ULL oa[8];                             // 4 m-rows x 4 d (2 f32x2 pairs)
    #pragma unroll
    for (int i = 0; i < 8; i++) oa[i] = 0ull;
    float den_t = 0.f;

    int ntiles = (chunk < 16) ? (512 / TPp) : 1;
    int pchunk0 = chunk * 512;
    __syncthreads();

    for (int tile = 0; tile < ntiles; tile++) {
        int p0 = pchunk0 + tile * TPp;

        // load K + V tiles (swizzled store)
        #pragma unroll
        for (int i = 0; i < 8; i++) {
            int idx = t + i * 128;
            int r = idx >> 5, c = idx & 31;
            int pg = p0 + r;
            float4 kv, vv;
            if (pg < PP) {
                size_t off = ((size_t)h * PP + pg) * DD + c * 4;
                kv = *(const float4*)(cacheK + off);
                vv = *(const float4*)(cacheV + off);
            } else if (pg < PTOT) {
                int mm2 = pg - PP;
                kv = *(const float4*)(g_k + mm2 * NN + h * DD + c * 4);
                vv = *(const float4*)(g_v + mm2 * NN + h * DD + c * 4);
            } else {
                kv = make_float4(0.f, 0.f, 0.f, 0.f);
                vv = kv;
            }
            int cs = SWZ(r, c);
            *(float4*)&Ks[r * 128 + cs * 4] = kv;
            *(float4*)&Vs[r * 128 + cs * 4] = vv;
        }
        __syncthreads();

        // scores: thread computes s[sm][pq*4 .. pq*4+3]
        ULL a[4] = {0ull, 0ull, 0ull, 0ull};
        #pragma unroll
        for (int kq = 0; kq < 32; kq++) {
            const ULL* qp = (const ULL*)&qs[sm][kq * 4];
            ULL q0 = qp[0], q1 = qp[1];
            #pragma unroll
            for (int j = 0; j < 4; j++) {
                int p = pq * 4 + j;
                const ULL* kp = (const ULL*)&Ks[p * 128 + SWZ(p, kq) * 4];
                fma2(a[j], q0, kp[0]);
                fma2(a[j], q1, kp[1]);
            }
        }
        #pragma unroll
        for (int j = 0; j < 4; j++) {
            float2 f = unpack2(a[j]);
            float s = f.x + f.y;
            int p = pq * 4 + j;
            float e = ((p0 + p) < PTOT) ? __expf(s) : 0.f;
            den_t += e;
            st[p][sm] = e;
        }
        __syncthreads();

        // O partial accumulate: warp owns m = warp*4..+3, lane owns d = lane*4..+3
        #pragma unroll
        for (int p = 0; p < TPp; p++) {
            float4 sv = *(const float4*)&st[p][warp * 4];      // broadcast
            const ULL* vp = (const ULL*)&Vs[p * 128 + SWZ(p, lane) * 4];
            ULL v0 = vp[0], v1 = vp[1];
            ULL s0 = pack2(sv.x, sv.x), s1 = pack2(sv.y, sv.y);
            ULL s2 = pack2(sv.z, sv.z), s3 = pack2(sv.w, sv.w);
            fma2(oa[0], v0, s0); fma2(oa[1], v1, s0);
            fma2(oa[2], v0, s1); fma2(oa[3], v1, s1);
            fma2(oa[4], v0, s2); fma2(oa[5], v1, s2);
            fma2(oa[6], v0, s3); fma2(oa[7], v1, s3);
        }
        __syncthreads();
    }

    // write O partials (exclusive slice -> plain stores, deterministic)
    float* np = g_nump + (((size_t)chunk * HH + h) * MM + warp * 4) * DD + lane * 4;
    #pragma unroll
    for (int mi = 0; mi < 4; mi++) {
        float2 lo = unpack2(oa[mi * 2]), hi = unpack2(oa[mi * 2 + 1]);
        *(float4*)(np + mi * DD) = make_float4(lo.x, lo.y, hi.x, hi.y);
    }
    // denominator partial: reduce the 8-thread group sharing m = sm
    for (int o = 4; o; o >>= 1) den_t += __shfl_down_sync(0xffffffffu, den_t, o, 8);
    if (pq == 0) g_denp[(chunk * HH + h) * MM + sm] = den_t;
}

// ============================================================
// K4: combine partials, divide, write output [M, N]
// ============================================================
__global__ __launch_bounds__(256) void final_kernel(float* __restrict__ out) {
    int idx = blockIdx.x * 256 + threadIdx.x;   // 0..65535
    int m = idx >> 12;
    int hd = idx & 4095;
    int h = hd >> 7, d = hd & 127;
    float num = 0.f, den = 0.f;
    #pragma unroll
    for (int c = 0; c < NCHUNK; c++) {
        num += g_nump[(((size_t)c * HH + h) * MM + m) * DD + d];
        den += g_denp[(c * HH + h) * MM + m];
    }
    out[idx] = num / den;
}

// ============================================================
extern "C" void kernel_launch(void* const* d_in, const int* in_sizes, int n_in,
                              void* d_out, int out_size) {
    const float* X  = (const float*)d_in[0];
    const float* Wq = (const float*)d_in[1];
    const float* Wk = (const float*)d_in[2];
    const float* Wv = (const float*)d_in[3];
    const float* cK = (const float*)d_in[4];
    const float* cV = (const float*)d_in[5];
    float* out = (float*)d_out;

    rms_kernel<<<MM, 256>>>(X);
    qkv_kernel<<<768, 256>>>(X, Wq, Wk, Wv);
    attn_kernel<<<dim3(NCHUNK, HH, 1), 128>>>(cK, cV);
    final_kernel<<<(MM * NN) / 256, 256>>>(out);
}

// round 7
// speedup vs baseline: 1.6320x; 1.6320x over previous
#include <cuda_runtime.h>

#define ULL unsigned long long

// ---------- packed f32x2 helpers (sm_100+ PTX) ----------
__device__ __forceinline__ void fma2(ULL &acc, ULL a, ULL b) {
    asm("fma.rn.f32x2 %0, %1, %2, %0;" : "+l"(acc) : "l"(a), "l"(b));
}
__device__ __forceinline__ float2 unpack2(ULL v) {
    float2 r; asm("mov.b64 {%0, %1}, %2;" : "=f"(r.x), "=f"(r.y) : "l"(v)); return r;
}
__device__ __forceinline__ ULL pack2(float x, float y) {
    ULL r; asm("mov.b64 %0, {%1, %2};" : "=l"(r) : "f"(x), "f"(y)); return r;
}

// ---------- problem dims ----------
#define MM 16
#define NN 4096
#define HH 32
#define DD 128
#define PP 8192
#define PTOT (PP + MM)        // 8208
#define NCHUNK 17             // 16 chunks of 512 cache + 1 chunk of new tokens

// ---------- device scratch ----------
__device__ float g_invr[MM];
__device__ float g_q[MM * NN];
__device__ float g_k[MM * NN];
__device__ float g_v[MM * NN];
__device__ float g_nump[NCHUNK * HH * MM * DD];
__device__ float g_denp[NCHUNK * HH * MM];

// ============================================================
// K1: per-row inverse RMS
// ============================================================
__global__ __launch_bounds__(256) void rms_kernel(const float* __restrict__ X) {
    int m = blockIdx.x;
    int t = threadIdx.x;
    float s = 0.f;
    const float4* Xr = (const float4*)(X + m * NN);
    for (int i = t; i < NN / 4; i += 256) {
        float4 v = Xr[i];
        s += v.x * v.x + v.y * v.y + v.z * v.z + v.w * v.w;
    }
    __shared__ float red[8];
    for (int o = 16; o; o >>= 1) s += __shfl_xor_sync(0xffffffffu, s, o);
    if ((t & 31) == 0) red[t >> 5] = s;
    __syncthreads();
    if (t == 0) {
        float tot = 0.f;
        #pragma unroll
        for (int i = 0; i < 8; i++) tot += red[i];
        g_invr[m] = rsqrtf(tot * (1.0f / (float)NN));
    }
}

// ============================================================
// K2: fused QKV projection.  out[m][j] = sum_k xnorm[m][k] * W[j][k]
// 768 blocks x 128 threads. 16 j per block, 4 j per warp.
// Double-buffered x staging (1 sync/chunk), register prefetch,
// LDS.128 x reads (bandwidth floor), fma2 everywhere.
// ============================================================
__global__ __launch_bounds__(128) void qkv_kernel(
    const float* __restrict__ X,
    const float* __restrict__ Wq,
    const float* __restrict__ Wk,
    const float* __restrict__ Wv)
{
    __shared__ float xs[2][MM][128];

    int b = blockIdx.x;
    int wsel  = b >> 8;            // 0=q, 1=k, 2=v
    int jbase = (b & 255) << 4;    // 16 columns per block
    const float* W   = (wsel == 0) ? Wq : (wsel == 1) ? Wk : Wv;
    float*       Out = (wsel == 0) ? g_q : (wsel == 1) ? g_k : g_v;

    int t = threadIdx.x, warp = t >> 5, lane = t & 31;
    int j0 = jbase + warp * 4;
    const float* Wb = W + (size_t)j0 * NN + lane * 4;

    // per-thread x-staging slots
    int mr[4], cr[4]; float ir[4];
    #pragma unroll
    for (int r = 0; r < 4; r++) {
        int idx = t + r * 128;
        mr[r] = idx >> 5; cr[r] = idx & 31;
        ir[r] = g_invr[mr[r]];
    }

    // prefetch chunk 0
    float4 xr[4];
    #pragma unroll
    for (int r = 0; r < 4; r++) {
        float4 v = *(const float4*)(X + mr[r] * NN + cr[r] * 4);
        v.x *= ir[r]; v.y *= ir[r]; v.z *= ir[r]; v.w *= ir[r];
        xr[r] = v;
    }

    ULL acc[4][MM];
    #pragma unroll
    for (int j = 0; j < 4; j++)
        #pragma unroll
        for (int m = 0; m < MM; m++) acc[j][m] = 0ull;

    for (int kc = 0; kc < NN / 128; kc++) {
        float* xbuf = &xs[kc & 1][0][0];
        #pragma unroll
        for (int r = 0; r < 4; r++)
            *(float4*)(xbuf + mr[r] * 128 + cr[r] * 4) = xr[r];
        __syncthreads();

        if (kc < NN / 128 - 1) {
            #pragma unroll
            for (int r = 0; r < 4; r++) {
                float4 v = *(const float4*)(X + mr[r] * NN + (kc + 1) * 128 + cr[r] * 4);
                v.x *= ir[r]; v.y *= ir[r]; v.z *= ir[r]; v.w *= ir[r];
                xr[r] = v;
            }
        }

        const float* wp = Wb + kc * 128;
        ulonglong2 w0 = *(const ulonglong2*)(wp);
        ulonglong2 w1 = *(const ulonglong2*)(wp + NN);
        ulonglong2 w2 = *(const ulonglong2*)(wp + 2 * NN);
        ulonglong2 w3 = *(const ulonglong2*)(wp + 3 * NN);

        #pragma unroll
        for (int m = 0; m < MM; m++) {
            ulonglong2 xv = *(const ulonglong2*)(xbuf + m * 128 + lane * 4);
            fma2(acc[0][m], xv.x, w0.x); fma2(acc[0][m], xv.y, w0.y);
            fma2(acc[1][m], xv.x, w1.x); fma2(acc[1][m], xv.y, w1.y);
            fma2(acc[2][m], xv.x, w2.x); fma2(acc[2][m], xv.y, w2.y);
            fma2(acc[3][m], xv.x, w3.x); fma2(acc[3][m], xv.y, w3.y);
        }
        // single sync per chunk: next store targets the other buffer,
        // and the re-use of this buffer is 2 syncs away.
    }

    // lane reduction: fold k-pair first, then 5-stage butterfly
    #pragma unroll
    for (int j = 0; j < 4; j++) {
        #pragma unroll
        for (int m = 0; m < MM; m++) {
            float2 f = unpack2(acc[j][m]);
            float s = f.x + f.y;
            #pragma unroll
            for (int o = 16; o; o >>= 1) s += __shfl_xor_sync(0xffffffffu, s, o);
            if (lane == 0) Out[m * NN + j0 + j] = s;
        }
    }
}

// ============================================================
// K3: attention partials, TP=16 tiles, register-prefetch pipeline.
// Swizzle c ^ ((p>>1)&7): conflict-free for store, score-K reads
// (lanes span distinct p>>1), and O-phase V reads.
// ============================================================
#define TP 16
__device__ __forceinline__ int SW(int r, int c) { return c ^ ((r >> 1) & 7); }

__global__ __launch_bounds__(128) void attn_kernel(
    const float* __restrict__ cacheK,
    const float* __restrict__ cacheV)
{
    __shared__ float qs[MM][132];
    __shared__ float Ks[TP * 128];
    __shared__ float Vs[TP * 128];
    __shared__ float st[TP][20];

    int chunk = blockIdx.x;                // 0..16
    int h     = blockIdx.y;
    int t = threadIdx.x, warp = t >> 5, lane = t & 31;
    int sm = t >> 3;                       // 0..15 (m for score phase)
    int tq = t & 7;                        // p-pair index
    int p_0 = tq * 2, p_1 = tq * 2 + 1;

    // load q tile for this head
    #pragma unroll
    for (int i = 0; i < 4; i++) {
        int idx = t + i * 128;
        int m = idx >> 5, c = idx & 31;
        *(float4*)&qs[m][c * 4] =
            *(const float4*)(g_q + m * NN + h * DD + c * 4);
    }

    ULL oa[8];
    #pragma unroll
    for (int i = 0; i < 8; i++) oa[i] = 0ull;
    float den = 0.f;

    int ntiles = (chunk < 16) ? (512 / TP) : 1;
    int pbase = chunk * 512;

    // prefetch tile 0 into registers
    float4 pk[4], pv[4];
    #pragma unroll
    for (int i = 0; i < 4; i++) {
        int r = warp + i * 4;
        if (chunk < 16) {
            size_t off = ((size_t)h * PP + pbase + r) * DD + lane * 4;
            pk[i] = *(const float4*)(cacheK + off);
            pv[i] = *(const float4*)(cacheV + off);
        } else {
            pk[i] = *(const float4*)(g_k + r * NN + h * DD + lane * 4);
            pv[i] = *(const float4*)(g_v + r * NN + h * DD + lane * 4);
        }
    }

    for (int tile = 0; tile < ntiles; tile++) {
        __syncthreads();   // previous tile's O-phase + st reads done
        #pragma unroll
        for (int i = 0; i < 4; i++) {
            int r = warp + i * 4;
            int cs = SW(r, lane);
            *(float4*)&Ks[r * 128 + cs * 4] = pk[i];
            *(float4*)&Vs[r * 128 + cs * 4] = pv[i];
        }
        __syncthreads();

        // prefetch next tile (cache chunks only; latency hidden by compute)
        if (tile + 1 < ntiles) {
            int p0n = pbase + (tile + 1) * TP;
            #pragma unroll
            for (int i = 0; i < 4; i++) {
                int r = warp + i * 4;
                size_t off = ((size_t)h * PP + p0n + r) * DD + lane * 4;
                pk[i] = *(const float4*)(cacheK + off);
                pv[i] = *(const float4*)(cacheV + off);
            }
        }

        // scores: thread computes p_0, p_1 for row sm
        ULL a0 = 0ull, a1 = 0ull;
        #pragma unroll
        for (int kq = 0; kq < 32; kq++) {
            ulonglong2 qv = *(const ulonglong2*)&qs[sm][kq * 4];
            ulonglong2 k0 = *(const ulonglong2*)&Ks[p_0 * 128 + SW(p_0, kq) * 4];
            ulonglong2 k1 = *(const ulonglong2*)&Ks[p_1 * 128 + SW(p_1, kq) * 4];
            fma2(a0, qv.x, k0.x); fma2(a0, qv.y, k0.y);
            fma2(a1, qv.x, k1.x); fma2(a1, qv.y, k1.y);
        }
        float2 f0 = unpack2(a0), f1 = unpack2(a1);
        float e0 = __expf(f0.x + f0.y);
        float e1 = __expf(f1.x + f1.y);
        den += e0 + e1;
        st[p_0][sm] = e0;
        st[p_1][sm] = e1;
        __syncthreads();

        // O accumulate: warp owns m = warp*4..+3, lane owns d = lane*4..+3
        #pragma unroll
        for (int p = 0; p < TP; p++) {
            float4 sv = *(const float4*)&st[p][warp * 4];          // broadcast
            ulonglong2 vv = *(const ulonglong2*)&Vs[p * 128 + SW(p, lane) * 4];
            ULL s0 = pack2(sv.x, sv.x), s1 = pack2(sv.y, sv.y);
            ULL s2 = pack2(sv.z, sv.z), s3 = pack2(sv.w, sv.w);
            fma2(oa[0], vv.x, s0); fma2(oa[1], vv.y, s0);
            fma2(oa[2], vv.x, s1); fma2(oa[3], vv.y, s1);
            fma2(oa[4], vv.x, s2); fma2(oa[5], vv.y, s2);
            fma2(oa[6], vv.x, s3); fma2(oa[7], vv.y, s3);
        }
    }

    // write O partials (exclusive slice -> plain stores, deterministic)
    float* np = g_nump + (((size_t)chunk * HH + h) * MM + warp * 4) * DD + lane * 4;
    #pragma unroll
    for (int mi = 0; mi < 4; mi++) {
        float2 lo = unpack2(oa[mi * 2]), hi = unpack2(oa[mi * 2 + 1]);
        *(float4*)(np + mi * DD) = make_float4(lo.x, lo.y, hi.x, hi.y);
    }
    // denominator partial: reduce the 8-thread group sharing row sm
    for (int o = 4; o; o >>= 1) den += __shfl_down_sync(0xffffffffu, den, o, 8);
    if (tq == 0) g_denp[(chunk * HH + h) * MM + sm] = den;
}

// ============================================================
// K4: combine partials, divide, write output [M, N]
// ============================================================
__global__ __launch_bounds__(256) void final_kernel(float* __restrict__ out) {
    int idx = blockIdx.x * 256 + threadIdx.x;   // 0..65535
    int m = idx >> 12;
    int hd = idx & 4095;
    int h = hd >> 7, d = hd & 127;
    float num = 0.f, den = 0.f;
    #pragma unroll
    for (int c = 0; c < NCHUNK; c++) {
        num += g_nump[(((size_t)c * HH + h) * MM + m) * DD + d];
        den += g_denp[(c * HH + h) * MM + m];
    }
    out[idx] = num / den;
}

// ============================================================
extern "C" void kernel_launch(void* const* d_in, const int* in_sizes, int n_in,
                              void* d_out, int out_size) {
    const float* X  = (const float*)d_in[0];
    const float* Wq = (const float*)d_in[1];
    const float* Wk = (const float*)d_in[2];
    const float* Wv = (const float*)d_in[3];
    const float* cK = (const float*)d_in[4];
    const float* cV = (const float*)d_in[5];
    float* out = (float*)d_out;

    rms_kernel<<<MM, 256>>>(X);
    qkv_kernel<<<768, 128>>>(X, Wq, Wk, Wv);
    attn_kernel<<<dim3(NCHUNK, HH, 1), 128>>>(cK, cV);
    final_kernel<<<(MM * NN) / 256, 256>>>(out);
}

// round 10
// speedup vs baseline: 2.2926x; 1.4048x over previous
#include <cuda_runtime.h>

#define ULL unsigned long long

// ---------- packed f32x2 helpers ----------
__device__ __forceinline__ void fma2(ULL &acc, ULL a, ULL b) {
    asm("fma.rn.f32x2 %0, %1, %2, %0;" : "+l"(acc) : "l"(a), "l"(b));
}
__device__ __forceinline__ ULL add2(ULL a, ULL b) {
    ULL r; asm("add.rn.f32x2 %0, %1, %2;" : "=l"(r) : "l"(a), "l"(b)); return r;
}
__device__ __forceinline__ float2 unpack2(ULL v) {
    float2 r; asm("mov.b64 {%0, %1}, %2;" : "=f"(r.x), "=f"(r.y) : "l"(v)); return r;
}
__device__ __forceinline__ ULL pack2(float x, float y) {
    ULL r; asm("mov.b64 %0, {%1, %2};" : "=l"(r) : "f"(x), "f"(y)); return r;
}
__device__ __forceinline__ void cp16(unsigned dst, const void* src) {
    asm volatile("cp.async.cg.shared.global [%0], [%1], 16;" :: "r"(dst), "l"(src));
}

// ---------- problem dims ----------
#define MM 16
#define NN 4096
#define HH 32
#define DD 128
#define PP 8192
#define PTOT (PP + MM)
#define NCHUNK 17
#define KSPLIT 4

// ---------- device scratch ----------
__device__ float g_invr[MM];
__device__ float g_part[KSPLIT * 3 * MM * NN];   // qkv k-split partials
__device__ float g_q[MM * NN];
__device__ float g_k[MM * NN];
__device__ float g_v[MM * NN];
__device__ float g_nump[NCHUNK * HH * MM * DD];
__device__ float g_denp[NCHUNK * HH * MM];

// ============================================================
// K1: per-row inverse RMS
// ============================================================
__global__ __launch_bounds__(256) void rms_kernel(const float* __restrict__ X) {
    int m = blockIdx.x;
    int t = threadIdx.x;
    float s = 0.f;
    const float4* Xr = (const float4*)(X + m * NN);
    for (int i = t; i < NN / 4; i += 256) {
        float4 v = Xr[i];
        s += v.x * v.x + v.y * v.y + v.z * v.z + v.w * v.w;
    }
    __shared__ float red[8];
    for (int o = 16; o; o >>= 1) s += __shfl_xor_sync(0xffffffffu, s, o);
    if ((t & 31) == 0) red[t >> 5] = s;
    __syncthreads();
    if (t == 0) {
        float tot = 0.f;
        #pragma unroll
        for (int i = 0; i < 8; i++) tot += red[i];
        g_invr[m] = rsqrtf(tot * (1.0f / (float)NN));
    }
}

// ============================================================
// K2: QKV projection, broadcast-operand design.
// grid 384 = 4 k-splits x (3 weights x 32 j-groups of 128).
// Lane owns output column j. W tile staged TRANSPOSED in smem
// (Wt[kpair][j], pad 129) and read once per k-pair into a register,
// reused across all 16 m with x as ULL broadcast -> fma2-bound.
// ============================================================
__global__ __launch_bounds__(128) void qkv_kernel(
    const float* __restrict__ X,
    const float* __restrict__ Wq,
    const float* __restrict__ Wk,
    const float* __restrict__ Wv)
{
    __shared__ ULL Wt[2][16][129];     // [buf][kpair][j] (transposed, padded)
    __shared__ ULL xq[2][MM][16];      // [buf][m][kpair]

    int bid = blockIdx.x;
    int kh = bid / 96;                 // k-split 0..3
    int g  = bid % 96;
    int wsel  = g >> 5;                // 0=q 1=k 2=v
    int jbase = (g & 31) << 7;         // *128
    const float* W = (wsel == 0) ? Wq : (wsel == 1) ? Wk : Wv;
    int koff = kh << 10;               // *1024

    int t = threadIdx.x;
    int jrow = t >> 3, cq = t & 7;     // W loader: 8-lane groups read 128B rows

    // prefetch chunk 0
    float4 wr[8];
    #pragma unroll
    for (int i = 0; i < 8; i++)
        wr[i] = *(const float4*)(W + (size_t)(jbase + jrow + 16 * i) * NN + koff + cq * 4);
    float iv = g_invr[jrow];           // jrow also serves as m for x loader (0..15)
    float4 xr = *(const float4*)(X + jrow * NN + koff + cq * 4);
    xr.x *= iv; xr.y *= iv; xr.z *= iv; xr.w *= iv;

    ULL acc[MM];
    #pragma unroll
    for (int m = 0; m < MM; m++) acc[m] = 0ull;

    for (int kc = 0; kc < 32; kc++) {
        int buf = kc & 1;
        #pragma unroll
        for (int i = 0; i < 8; i++) {
            Wt[buf][2 * cq][jrow + 16 * i]     = pack2(wr[i].x, wr[i].y);
            Wt[buf][2 * cq + 1][jrow + 16 * i] = pack2(wr[i].z, wr[i].w);
        }
        *(float4*)&xq[buf][jrow][2 * cq] = xr;
        __syncthreads();

        if (kc < 31) {
            int kb = koff + (kc + 1) * 32;
            #pragma unroll
            for (int i = 0; i < 8; i++)
                wr[i] = *(const float4*)(W + (size_t)(jbase + jrow + 16 * i) * NN + kb + cq * 4);
            xr = *(const float4*)(X + jrow * NN + kb + cq * 4);
            xr.x *= iv; xr.y *= iv; xr.z *= iv; xr.w *= iv;
        }

        #pragma unroll
        for (int kpp = 0; kpp < 8; kpp++) {
            ULL w0 = Wt[buf][2 * kpp][t];
            ULL w1 = Wt[buf][2 * kpp + 1][t];
            #pragma unroll
            for (int m = 0; m < MM; m++) {
                ulonglong2 xv = *(const ulonglong2*)&xq[buf][m][2 * kpp];
                fma2(acc[m], w0, xv.x);
                fma2(acc[m], w1, xv.y);
            }
        }
        // single sync per chunk: next store hits the other buffer; re-use of
        // this buffer is preceded by the next sync (program order covers reads).
    }

    float* dst = g_part + ((size_t)kh * 3 + wsel) * (MM * NN);
    #pragma unroll
    for (int m = 0; m < MM; m++) {
        float2 f = unpack2(acc[m]);
        dst[m * NN + jbase + t] = f.x + f.y;
    }
}

// ============================================================
// K2b: combine k-split partials -> g_q / g_k / g_v
// ============================================================
__global__ __launch_bounds__(256) void combine_kernel() {
    int idx = blockIdx.x * 256 + threadIdx.x;     // < 196608
    int sel = idx >> 16, r = idx & 65535;
    float v = g_part[(0 * 3 + sel) * 65536 + r]
            + g_part[(1 * 3 + sel) * 65536 + r]
            + g_part[(2 * 3 + sel) * 65536 + r]
            + g_part[(3 * 3 + sel) * 65536 + r];
    float* o = (sel == 0) ? g_q : (sel == 1) ? g_k : g_v;
    o[r] = v;
}

// ============================================================
// K3: attention partials. TP=32 rows/tile, block 128, grid (17,32).
// Score: lane owns p, warps split d in 4 chunks; K transposed+swizzled
//   in smem, K-pair in reg reused over 16 m with q broadcast.
//   Warp-private partials overlaid into that warp's own Kt rows.
// O: warps split (p x2, m x2); V row read once per p, score broadcasts.
// V via cp.async (latency hidden under score phase); K reg-prefetched.
// ============================================================
__global__ __launch_bounds__(128, 3) void attn_kernel(
    const float* __restrict__ cacheK,
    const float* __restrict__ cacheV)
{
    __shared__ ULL qs2[MM][64];        // [m][kpair] q pairs (broadcast reads)
    __shared__ ULL Kt[64][32];         // [kpair][p^(kp>>1)]; reused for score
                                       // partials and final O exchange
    __shared__ float Vs[32][DD];
    __shared__ float st[32][18];       // exp scores [p][m], padded
    __shared__ float den4[4][16];

    int chunk = blockIdx.x, h = blockIdx.y;
    int t = threadIdx.x, w = t >> 5, lane = t & 31;
    int rm = t & 15, rpg = t >> 4;     // reduce-phase: m, p-group (0..7)
    int pg2 = w & 1, mg = w >> 1;      // O-phase: p-half, m-half

    // q staging: qs2[m][kp]
    #pragma unroll
    for (int i = 0; i < 4; i++) {
        int idx = t + i * 128;
        int m = idx >> 5, cq = idx & 31;
        float4 v = *(const float4*)(g_q + m * NN + h * DD + cq * 4);
        *(float4*)&qs2[m][2 * cq] = v;
    }

    ULL oa[16];
    #pragma unroll
    for (int i = 0; i < 16; i++) oa[i] = 0ull;
    float den_t = 0.f;

    int ntiles = (chunk < 16) ? 16 : 1;
    int pbase = chunk * 512;

    // prefetch K tile 0 (loader: r = w + 4i, cq = lane)
    float4 pk[8];
    #pragma unroll
    for (int i = 0; i < 8; i++) {
        int r = w + 4 * i;
        if (chunk < 16)
            pk[i] = *(const float4*)(cacheK + ((size_t)h * PP + pbase + r) * DD + lane * 4);
        else if (r < MM)
            pk[i] = *(const float4*)(g_k + r * NN + h * DD + lane * 4);
        else
            pk[i] = make_float4(0.f, 0.f, 0.f, 0.f);
    }

    for (int tile = 0; tile < ntiles; tile++) {
        int p0 = pbase + tile * 32;
        __syncthreads();                       // prev tile fully consumed
        // K -> Kt (transpose + swizzle col = r ^ (kp>>1))
        #pragma unroll
        for (int i = 0; i < 8; i++) {
            int r = w + 4 * i;
            int col = (r ^ lane) & 31;
            Kt[2 * lane][col]     = pack2(pk[i].x, pk[i].y);
            Kt[2 * lane + 1][col] = pack2(pk[i].z, pk[i].w);
        }
        __syncthreads();                       // Kt ready; prev O reads done
        // V cp.async for THIS tile (hidden under score phase)
        #pragma unroll
        for (int i = 0; i < 8; i++) {
            int r = w + 4 * i;
            unsigned dst = (unsigned)__cvta_generic_to_shared(&Vs[r][lane * 4]);
            if (chunk < 16)
                cp16(dst, cacheV + ((size_t)h * PP + p0 + r) * DD + lane * 4);
            else if (r < MM)
                cp16(dst, g_v + r * NN + h * DD + lane * 4);
            else
                *(float4*)&Vs[r][lane * 4] = make_float4(0.f, 0.f, 0.f, 0.f);
        }
        asm volatile("cp.async.commit_group;");
        // prefetch next K tile
        if (tile + 1 < ntiles) {
            #pragma unroll
            for (int i = 0; i < 8; i++) {
                int r = w + 4 * i;
                pk[i] = *(const float4*)(cacheK + ((size_t)h * PP + p0 + 32 + r) * DD + lane * 4);
            }
        }

        // ---- score phase: warp w handles kp in [16w, 16w+16) ----
        ULL as[MM];
        #pragma unroll
        for (int m = 0; m < MM; m++) as[m] = 0ull;
        #pragma unroll
        for (int kpp = 0; kpp < 8; kpp++) {
            int kpA = w * 16 + 2 * kpp;
            int col = (lane ^ (kpA >> 1)) & 31;
            ULL kA = Kt[kpA][col];
            ULL kB = Kt[kpA + 1][col];
            #pragma unroll
            for (int m = 0; m < MM; m++) {
                ulonglong2 qv = *(const ulonglong2*)&qs2[m][kpA];
                fma2(as[m], kA, qv.x);
                fma2(as[m], kB, qv.y);
            }
        }
        // overlay score partials into this warp's OWN Kt rows (private)
        #pragma unroll
        for (int m = 0; m < MM; m++)
            Kt[w * 16 + m][(lane ^ m) & 31] = as[m];
        __syncthreads();

        // ---- reduce partials -> exp -> st ----
        #pragma unroll
        for (int i = 0; i < 4; i++) {
            int p = rpg * 4 + i;
            int col = (p ^ rm) & 31;
            ULL ssum = add2(add2(Kt[rm][col],      Kt[16 + rm][col]),
                            add2(Kt[32 + rm][col], Kt[48 + rm][col]));
            float2 f = unpack2(ssum);
            float sc = f.x + f.y;
            float e = ((p0 + p) < PTOT) ? __expf(sc) : 0.f;
            den_t += e;
            st[p][rm] = e;
        }
        asm volatile("cp.async.wait_group 0;");
        __syncthreads();                       // st + Vs ready

        // ---- O phase: warp (pg2, mg): 16 p x 8 m ----
        #pragma unroll
        for (int pp = 0; pp < 16; pp++) {
            int p = pg2 * 16 + pp;
            ulonglong2 vv = *(const ulonglong2*)&Vs[p][lane * 4];
            #pragma unroll
            for (int a = 0; a < 4; a++) {
                float2 sv = *(const float2*)&st[p][mg * 8 + 2 * a];
                ULL sa = pack2(sv.x, sv.x);
                ULL sb = pack2(sv.y, sv.y);
                fma2(oa[4 * a + 0], vv.x, sa);
                fma2(oa[4 * a + 1], vv.y, sa);
                fma2(oa[4 * a + 2], vv.x, sb);
                fma2(oa[4 * a + 3], vv.y, sb);
            }
        }
    }

    // ---- cross-warp O reduction (p-halves) via Kt as scratch ----
    ULL* ow = &Kt[0][0];                        // 2048 ULLs free now
    if (pg2 == 1) {
        #pragma unroll
        for (int mi = 0; mi < 8; mi++) {
            ulonglong2 v;
            v.x = oa[2 * mi]; v.y = oa[2 * mi + 1];
            *(ulonglong2*)&ow[((mg * 8 + mi) * 32 + lane) * 2] = v;
        }
    }
    // den: lanes l and l+16 share m
    den_t += __shfl_xor_sync(0xffffffffu, den_t, 16);
    if (lane < 16) den4[w][lane] = den_t;
    __syncthreads();

    if (pg2 == 0) {
        float* np = g_nump + (((size_t)chunk * HH + h) * MM + mg * 8) * DD + lane * 4;
        #pragma unroll
        for (int mi = 0; mi < 8; mi++) {
            ulonglong2 pv = *(const ulonglong2*)&ow[((mg * 8 + mi) * 32 + lane) * 2];
            ULL r0 = add2(oa[2 * mi], pv.x);
            ULL r1 = add2(oa[2 * mi + 1], pv.y);
            float2 lo = unpack2(r0), hi = unpack2(r1);
            *(float4*)(np + mi * DD) = make_float4(lo.x, lo.y, hi.x, hi.y);
        }
    }
    if (t < 16) {
        float d = den4[0][t] + den4[1][t] + den4[2][t] + den4[3][t];
        g_denp[(chunk * HH + h) * MM + t] = d;
    }
}

// ============================================================
// K4: combine partials, divide, write output [M, N]
// ============================================================
__global__ __launch_bounds__(256) void final_kernel(float* __restrict__ out) {
    int idx = blockIdx.x * 256 + threadIdx.x;
    int m = idx >> 12;
    int hd = idx & 4095;
    int h = hd >> 7, d = hd & 127;
    float num = 0.f, den = 0.f;
    #pragma unroll
    for (int c = 0; c < NCHUNK; c++) {
        num += g_nump[(((size_t)c * HH + h) * MM + m) * DD + d];
        den += g_denp[(c * HH + h) * MM + m];
    }
    out[idx] = num / den;
}

// ============================================================
extern "C" void kernel_launch(void* const* d_in, const int* in_sizes, int n_in,
                              void* d_out, int out_size) {
    const float* X  = (const float*)d_in[0];
    const float* Wq = (const float*)d_in[1];
    const float* Wk = (const float*)d_in[2];
    const float* Wv = (const float*)d_in[3];
    const float* cK = (const float*)d_in[4];
    const float* cV = (const float*)d_in[5];
    float* out = (float*)d_out;

    rms_kernel<<<MM, 256>>>(X);
    qkv_kernel<<<384, 128>>>(X, Wq, Wk, Wv);
    combine_kernel<<<768, 256>>>();
    attn_kernel<<<dim3(NCHUNK, HH, 1), 128>>>(cK, cV);
    final_kernel<<<(MM * NN) / 256, 256>>>(out);
}